// round 2
// baseline (speedup 1.0000x reference)
#include <cuda_runtime.h>

// Problem constants (fixed by setup_inputs)
#define B_    16
#define T_    512
#define D_    384
#define M_    4096
#define MEL_  1536

#define OFF_DEC   (B_ * MEL_ * D_)        // 9437184
#define OFF_PITCH (OFF_DEC + B_)          // 9437200

// Scratch: l -> source t map per batch (-1 = zero row). Device global, no alloc.
__device__ int g_map[B_ * MEL_];

// Kernel 1: per-batch scan of durations, dec_lens, map scatter, pitch averaging.
// grid = B_, block = T_ (512 threads = 16 warps)
__global__ void prep_kernel(const int* __restrict__ durs,
                            const float* __restrict__ pitch,
                            float* __restrict__ out) {
    __shared__ int s_warp[16];     // per-warp totals
    __shared__ int s_total;

    const int b    = blockIdx.x;
    const int t    = threadIdx.x;
    const int lane = t & 31;
    const int wid  = t >> 5;

    int d = durs[b * T_ + t];
    // reps = int(float(d)/1.0 + 0.5) == d for d in [0,8)

    // Warp-level inclusive scan
    int scan = d;
    #pragma unroll
    for (int off = 1; off < 32; off <<= 1) {
        int v = __shfl_up_sync(0xFFFFFFFFu, scan, off);
        if (lane >= off) scan += v;
    }
    if (lane == 31) s_warp[wid] = scan;
    __syncthreads();

    // Warp 0 scans the 16 warp totals (exclusive prefix)
    if (wid == 0 && lane < 16) {
        int w = s_warp[lane];
        int ws = w;
        #pragma unroll
        for (int off = 1; off < 16; off <<= 1) {
            int v = __shfl_up_sync(0xFFFFu, ws, off);
            if (lane >= off) ws += v;
        }
        s_warp[lane] = ws - w;        // exclusive prefix of warp totals
        if (lane == 15) s_total = ws; // grand total
    }
    __syncthreads();

    const int incl  = scan + s_warp[wid];   // inclusive scan of durations
    const int end   = incl;
    const int start = incl - d;
    const int total = s_total;

    if (t == 0) {
        out[OFF_DEC + b] = (float)min(total, MEL_);
    }

    // Init map to -1 (zero rows), then scatter t into its [start,end) range.
    for (int i = t; i < MEL_; i += T_) g_map[b * MEL_ + i] = -1;
    __syncthreads();

    const int e2 = min(end, MEL_);
    for (int l = start; l < e2; ++l) g_map[b * MEL_ + l] = t;

    // Pitch averaging over segment [start,end) of pitch[b, 0, :]
    const float* p = pitch + b * M_;
    float sum = 0.0f, cnt = 0.0f;
    for (int i = start; i < end; ++i) {
        float v = p[i];
        sum += v;
        cnt += (v != 0.0f) ? 1.0f : 0.0f;
    }
    out[OFF_PITCH + b * T_ + t] = (cnt == 0.0f) ? 0.0f : (sum / cnt);
}

// Kernel 2: enc_rep gather. Each 96-thread group copies one row of D_=384
// floats (96 float4). grid = (MEL_/4, B_), block = (96, 4).
__global__ void gather_kernel(const float4* __restrict__ enc,
                              float4* __restrict__ out) {
    const int lane = threadIdx.x;                       // 0..95
    const int l = blockIdx.x * 4 + threadIdx.y;         // 0..MEL_-1
    const int b = blockIdx.y;

    const int t = g_map[b * MEL_ + l];                  // warp broadcast
    float4 v;
    if (t >= 0) {
        v = enc[(b * T_ + t) * (D_ / 4) + lane];
    } else {
        v = make_float4(0.0f, 0.0f, 0.0f, 0.0f);
    }
    out[(b * MEL_ + l) * (D_ / 4) + lane] = v;
}

extern "C" void kernel_launch(void* const* d_in, const int* in_sizes, int n_in,
                              void* d_out, int out_size) {
    const float* enc_out   = (const float*)d_in[0];   // (16, 512, 384) f32
    const int*   durations = (const int*)d_in[1];     // (16, 512) i32
    const float* pitch     = (const float*)d_in[2];   // (16, 1, 4096) f32
    // d_in[3] (mel_max_len) is a compile-time constant 1536 here.

    float* out = (float*)d_out;

    prep_kernel<<<B_, T_>>>(durations, pitch, out);

    dim3 block(96, 4);
    dim3 grid(MEL_ / 4, B_);
    gather_kernel<<<grid, block>>>((const float4*)enc_out, (float4*)out);
}

// round 3
// speedup vs baseline: 1.1205x; 1.1205x over previous
#include <cuda_runtime.h>

// Problem constants (fixed by setup_inputs)
#define B_    16
#define T_    512
#define D_    384
#define M_    4096
#define MEL_  1536

#define OFF_DEC   (B_ * MEL_ * D_)        // 9437184
#define OFF_PITCH (OFF_DEC + B_)          // 9437200

// Scratch: l -> source t map per batch (-1 = zero row). Device global, no alloc.
__device__ int g_map[B_ * MEL_];

// Kernel 1: per-batch scan of durations, dec_lens, map scatter, pitch averaging.
// grid = B_, block = T_ (512 threads = 16 warps)
__global__ void prep_kernel(const int* __restrict__ durs,
                            const float* __restrict__ pitch,
                            float* __restrict__ out) {
    __shared__ int s_warp[16];     // per-warp totals
    __shared__ int s_total;

    const int b    = blockIdx.x;
    const int t    = threadIdx.x;
    const int lane = t & 31;
    const int wid  = t >> 5;

    int d = durs[b * T_ + t];
    // reps = int(float(d)/1.0 + 0.5) == d for d in [0,8)

    // Warp-level inclusive scan
    int scan = d;
    #pragma unroll
    for (int off = 1; off < 32; off <<= 1) {
        int v = __shfl_up_sync(0xFFFFFFFFu, scan, off);
        if (lane >= off) scan += v;
    }
    if (lane == 31) s_warp[wid] = scan;
    __syncthreads();

    // Warp 0 scans the 16 warp totals (exclusive prefix)
    if (wid == 0 && lane < 16) {
        int w = s_warp[lane];
        int ws = w;
        #pragma unroll
        for (int off = 1; off < 16; off <<= 1) {
            int v = __shfl_up_sync(0xFFFFu, ws, off);
            if (lane >= off) ws += v;
        }
        s_warp[lane] = ws - w;        // exclusive prefix of warp totals
        if (lane == 15) s_total = ws; // grand total
    }
    __syncthreads();

    const int incl  = scan + s_warp[wid];   // inclusive scan of durations
    const int end   = incl;
    const int start = incl - d;
    const int total = s_total;

    if (t == 0) {
        out[OFF_DEC + b] = (float)min(total, MEL_);
    }

    // Init map to -1 (zero rows), then scatter t into its [start,end) range.
    for (int i = t; i < MEL_; i += T_) g_map[b * MEL_ + i] = -1;
    __syncthreads();

    const int e2 = min(end, MEL_);
    for (int l = start; l < e2; ++l) g_map[b * MEL_ + l] = t;

    // Pitch averaging over segment [start,end) of pitch[b, 0, :]
    const float* p = pitch + b * M_;
    float sum = 0.0f, cnt = 0.0f;
    for (int i = start; i < end; ++i) {
        float v = p[i];
        sum += v;
        cnt += (v != 0.0f) ? 1.0f : 0.0f;
    }
    out[OFF_PITCH + b * T_ + t] = (cnt == 0.0f) ? 0.0f : (sum / cnt);
}

// Kernel 2: enc_rep gather with 4-way ILP per thread.
// Each thread handles 4 consecutive l-rows (same lane column), so it issues
// 1 int4 map load + 4 independent float4 loads + 4 float4 stores.
// grid = (MEL_/16, B_), block = (96, 4)  -> 1536 blocks of 384 threads.
__global__ void gather_kernel(const float4* __restrict__ enc,
                              float4* __restrict__ out) {
    const int lane = threadIdx.x;                         // 0..95 (float4 col)
    const int b    = blockIdx.y;
    const int l0   = blockIdx.x * 16 + threadIdx.y * 4;   // first of 4 rows

    // Vectorized map load: 4 consecutive ints, 16B-aligned (l0 % 4 == 0).
    const int4 tm = *(const int4*)&g_map[b * MEL_ + l0];
    const int tt[4] = { tm.x, tm.y, tm.z, tm.w };

    const float4 zero = make_float4(0.0f, 0.0f, 0.0f, 0.0f);
    float4 v[4];
    #pragma unroll
    for (int i = 0; i < 4; ++i) {
        v[i] = (tt[i] >= 0) ? enc[(b * T_ + tt[i]) * (D_ / 4) + lane] : zero;
    }

    float4* o = out + (b * MEL_ + l0) * (D_ / 4) + lane;
    #pragma unroll
    for (int i = 0; i < 4; ++i) {
        o[i * (D_ / 4)] = v[i];
    }
}

extern "C" void kernel_launch(void* const* d_in, const int* in_sizes, int n_in,
                              void* d_out, int out_size) {
    const float* enc_out   = (const float*)d_in[0];   // (16, 512, 384) f32
    const int*   durations = (const int*)d_in[1];     // (16, 512) i32
    const float* pitch     = (const float*)d_in[2];   // (16, 1, 4096) f32
    // d_in[3] (mel_max_len) is a compile-time constant 1536 here.

    float* out = (float*)d_out;

    prep_kernel<<<B_, T_>>>(durations, pitch, out);

    dim3 block(96, 4);
    dim3 grid(MEL_ / 16, B_);
    gather_kernel<<<grid, block>>>((const float4*)enc_out, (float4*)out);
}